// round 15
// baseline (speedup 1.0000x reference)
#include <cuda_runtime.h>
#include <cuda_fp16.h>
#include <math.h>

#define VN 50257
#define VPAD 50304   // 393 * 128
#define KN 512
#define DN 768
#define RN 192
#define KD 960       // DN + RN
#define RSU 40       // ubgemm smem row stride (halves)
#define RSM 72       // maingemm smem row stride (halves), BK=64

// ---------------- scratch (static device globals; no allocation) ----------------
__device__ __half g_A16[KN * KD];
__device__ __half g_B16[(size_t)VPAD * KD];
__device__ float g_AA[KN];
__device__ float g_BB[VPAD];
__device__ float g_F[(size_t)KN * VPAD];      // scale*s + bias - 0.3*mah + 0.3*2ab/eps
__device__ __half g_Kh[(size_t)KN * VPAD];    // exp(2ab/eps - sh); 0 in pad cols
__device__ float g_u[KN];
__device__ float g_v[VPAD];
__device__ float g_vden[2][VPAD];
__device__ float g_lvl[VPAD];
__device__ float g_rinv[KN];
__device__ int   g_idflag;

// ---------------- helpers ----------------
__device__ __forceinline__ void cp16(void* sm, const void* gp) {
    unsigned sa = (unsigned)__cvta_generic_to_shared(sm);
    asm volatile("cp.async.cg.shared.global [%0], [%1], 16;\n" :: "r"(sa), "l"(gp));
}
__device__ __forceinline__ void cpcommit() { asm volatile("cp.async.commit_group;\n"); }
template<int N> __device__ __forceinline__ void cpwait() {
    asm volatile("cp.async.wait_group %0;\n" :: "n"(N));
}
__device__ __forceinline__ void mma16816h(float c[4], const unsigned a[4], const unsigned b[2]) {
    asm volatile(
        "mma.sync.aligned.m16n8k16.row.col.f32.f16.f16.f32 "
        "{%0,%1,%2,%3}, {%4,%5,%6,%7}, {%8,%9}, {%0,%1,%2,%3};\n"
        : "+f"(c[0]), "+f"(c[1]), "+f"(c[2]), "+f"(c[3])
        : "r"(a[0]), "r"(a[1]), "r"(a[2]), "r"(a[3]), "r"(b[0]), "r"(b[1]));
}
__device__ __forceinline__ void ldsm4(unsigned r[4], const __half* p) {
    unsigned a = (unsigned)__cvta_generic_to_shared(p);
    asm volatile("ldmatrix.sync.aligned.m8n8.x4.shared.b16 {%0,%1,%2,%3}, [%4];\n"
                 : "=r"(r[0]), "=r"(r[1]), "=r"(r[2]), "=r"(r[3]) : "r"(a));
}
__device__ __forceinline__ float eps_of(float le) {
    return ((le > 20.f) ? le : log1pf(expf(le))) + 0.001f;
}

// ---------------- init ----------------
__global__ void k_init() { g_idflag = 1; }

__global__ void k_idcheck(const float* __restrict__ Wp) {
    int stride = gridDim.x * blockDim.x;
    for (int i = blockIdx.x * blockDim.x + threadIdx.x; i < DN * DN; i += stride) {
        float e = ((i / DN) == (i % DN)) ? 1.f : 0.f;
        if (Wp[i] != e) g_idflag = 0;
    }
}

// ---------------- anchors: normalize, Ua = a@U, AA from rounded fp16 ----------------
__global__ void k_anchors(const float* __restrict__ anch, const float* __restrict__ U) {
    __shared__ float sa[DN];
    __shared__ float sred[256];
    int k = blockIdx.x, tid = threadIdx.x;

    float ss = 0.f;
    for (int d = tid; d < DN; d += 256) { float x = anch[k * DN + d]; sa[d] = x; ss += x * x; }
    sred[tid] = ss; __syncthreads();
    for (int o = 128; o > 0; o >>= 1) { if (tid < o) sred[tid] += sred[tid + o]; __syncthreads(); }
    float inv = 1.f / fmaxf(sqrtf(sred[0]), 1e-12f);
    __syncthreads();
    float aa = 0.f;
    for (int d = tid; d < DN; d += 256) {
        float x = sa[d] * inv; sa[d] = x;
        __half h = __float2half(x);
        g_A16[k * KD + d] = h;
        float hr = __half2float(h);
        aa += hr * hr;
    }
    __syncthreads();
    if (tid < RN) {
        float acc = 0.f;
        for (int d = 0; d < DN; d++) acc += sa[d] * U[d * RN + tid];
        __half h = __float2half(acc);
        g_A16[k * KD + DN + tid] = h;
        float hr = __half2float(h);
        aa += hr * hr;
    }
    sred[tid] = aa; __syncthreads();
    for (int o = 128; o > 0; o >>= 1) { if (tid < o) sred[tid] += sred[tid + o]; __syncthreads(); }
    if (tid == 0) g_AA[k] = sred[0];
}

// ---------------- w_norm: warp-per-row, fp16 out, BB = sum of rounded squares ----------------
__global__ __launch_bounds__(256) void k_wnorm(const float* __restrict__ we,
                                               const float* __restrict__ Wp) {
    int warp = threadIdx.x >> 5, lane = threadIdx.x & 31;
    int v = blockIdx.x * 8 + warp;
    if (v >= VPAD) return;
    size_t gb = (size_t)v * KD;
    if (v >= VN) {
        #pragma unroll
        for (int c = 0; c < 6; c++) {
            int d = c * 128 + lane * 4;
            *(uint2*)&g_B16[gb + d] = make_uint2(0u, 0u);
        }
        if (lane == 0) g_BB[v] = 0.f;
        return;
    }
    int flag = g_idflag;
    float4 x[6];
    if (flag) {
        #pragma unroll
        for (int c = 0; c < 6; c++)
            x[c] = *(const float4*)&we[(size_t)v * DN + c * 128 + lane * 4];
    } else {
        for (int c = 0; c < 6; c++) {
            float r[4];
            for (int u2 = 0; u2 < 4; u2++) {
                int d = c * 128 + lane * 4 + u2;
                float acc = 0.f;
                for (int j = 0; j < DN; j++) acc += we[(size_t)v * DN + j] * Wp[d * DN + j];
                r[u2] = acc;
            }
            x[c] = make_float4(r[0], r[1], r[2], r[3]);
        }
    }
    float ss = 0.f;
    #pragma unroll
    for (int c = 0; c < 6; c++)
        ss += x[c].x * x[c].x + x[c].y * x[c].y + x[c].z * x[c].z + x[c].w * x[c].w;
    #pragma unroll
    for (int o = 16; o > 0; o >>= 1) ss += __shfl_xor_sync(0xffffffffu, ss, o);
    float inv = 1.f / fmaxf(sqrtf(ss), 1e-12f);
    float bb = 0.f;
    #pragma unroll
    for (int c = 0; c < 6; c++) {
        int d = c * 128 + lane * 4;
        float vl[4] = {x[c].x * inv, x[c].y * inv, x[c].z * inv, x[c].w * inv};
        __half h[4];
        #pragma unroll
        for (int t = 0; t < 4; t++) {
            h[t] = __float2half(vl[t]);
            float hr = __half2float(h[t]);
            bb += hr * hr;
        }
        *(__half2*)&g_B16[gb + d]     = __half2(h[0], h[1]);
        *(__half2*)&g_B16[gb + d + 2] = __half2(h[2], h[3]);
    }
    #pragma unroll
    for (int o = 16; o > 0; o >>= 1) bb += __shfl_xor_sync(0xffffffffu, bb, o);
    if (lane == 0) g_BB[v] = bb;
}

// ---------------- Ub = w_norm @ U (fp16, ldmatrix, double-buffered), fused BB add ----------------
// dyn smem: 2 * (5120 + 7680) halves + 128 floats = 51712 B
__global__ __launch_bounds__(256) void k_ubgemm(const float* __restrict__ U) {
    extern __shared__ __half dsm[];
    float* sBB = (float*)(dsm + 25600);

    int bm = blockIdx.x * 128;
    int tid = threadIdx.x;
    int w = tid >> 5, lane = tid & 31;
    int g = lane >> 2, q = lane & 3;
    int wm = w >> 2, wn = w & 3;
    int mi = lane >> 3, lr = lane & 7;
    int aoff = (wm * 64 + (mi & 1) * 8 + lr) * RSU + (mi >> 1) * 8;
    int boff = (wn * 48 + (mi >> 1) * 8 + lr) * RSU + (mi & 1) * 8;
    if (tid < 128) sBB[tid] = 0.f;

    float acc[4][6][4];
    #pragma unroll
    for (int i = 0; i < 4; i++)
        #pragma unroll
        for (int j = 0; j < 6; j++)
            #pragma unroll
            for (int c = 0; c < 4; c++) acc[i][j][c] = 0.f;

    auto load_stage = [&](int s, int buf) {
        __half* sW = dsm + buf * 12800;
        __half* sU = sW + 5120;
        int k0 = s * 32;
        for (int c = tid; c < 512; c += 256) {
            int row = c >> 2, ch = c & 3;
            cp16(sW + row * RSU + ch * 8, g_B16 + (size_t)(bm + row) * KD + k0 + ch * 8);
        }
        for (int idx = tid; idx < 32 * RN; idx += 256) {
            int kp = idx / RN, n = idx % RN;
            sU[n * RSU + kp] = __float2half(U[(k0 + kp) * RN + n]);
        }
    };

    load_stage(0, 0); cpcommit();
    for (int s = 0; s < 24; s++) {
        int buf = s & 1;
        if (s < 23) { load_stage(s + 1, buf ^ 1); cpcommit(); cpwait<1>(); }
        else        { cpwait<0>(); }
        __syncthreads();
        const __half* sW = dsm + buf * 12800;
        const __half* sU = sW + 5120;
        #pragma unroll
        for (int kk = 0; kk < 32; kk += 16) {
            unsigned ah[4][4], bh[6][2];
            #pragma unroll
            for (int i = 0; i < 4; i++)
                ldsm4(ah[i], sW + aoff + i * 16 * RSU + kk);
            #pragma unroll
            for (int jp = 0; jp < 3; jp++) {
                unsigned t[4];
                ldsm4(t, sU + boff + jp * 16 * RSU + kk);
                bh[2*jp][0] = t[0]; bh[2*jp][1] = t[1];
                bh[2*jp+1][0] = t[2]; bh[2*jp+1][1] = t[3];
            }
            #pragma unroll
            for (int i = 0; i < 4; i++)
                #pragma unroll
                for (int j = 0; j < 6; j++)
                    mma16816h(acc[i][j], ah[i], bh[j]);
        }
        __syncthreads();
    }

    #pragma unroll
    for (int i = 0; i < 4; i++) {
        int l0 = wm * 64 + i * 16 + g, l1 = l0 + 8;
        size_t m0 = (size_t)(bm + l0) * KD + DN;
        size_t m1 = (size_t)(bm + l1) * KD + DN;
        float p0 = 0.f, p1 = 0.f;
        #pragma unroll
        for (int j = 0; j < 6; j++) {
            int n0 = wn * 48 + j * 8 + 2 * q;
            __half h00 = __float2half(acc[i][j][0]);
            __half h01 = __float2half(acc[i][j][1]);
            __half h10 = __float2half(acc[i][j][2]);
            __half h11 = __float2half(acc[i][j][3]);
            float f00 = __half2float(h00), f01 = __half2float(h01);
            float f10 = __half2float(h10), f11 = __half2float(h11);
            p0 += f00 * f00 + f01 * f01;
            p1 += f10 * f10 + f11 * f11;
            g_B16[m0 + n0] = h00; g_B16[m0 + n0 + 1] = h01;
            g_B16[m1 + n0] = h10; g_B16[m1 + n0 + 1] = h11;
        }
        p0 += __shfl_xor_sync(0xffffffffu, p0, 1); p0 += __shfl_xor_sync(0xffffffffu, p0, 2);
        p1 += __shfl_xor_sync(0xffffffffu, p1, 1); p1 += __shfl_xor_sync(0xffffffffu, p1, 2);
        if (q == 0) { atomicAdd(&sBB[l0], p0); atomicAdd(&sBB[l1], p1); }
    }
    __syncthreads();
    if (tid < 128) g_BB[bm + tid] += sBB[tid];
}

// ---------------- main GEMM (fp16, BK=64, dual acc) + fused epilogue ----------------
__device__ __forceinline__ void mg_compute(const __half* sb, int aoff, int boff,
                                           float acc[4][4][4]) {
    const __half* sA = sb;
    const __half* sB = sb + 9216;
    #pragma unroll
    for (int kk = 0; kk < 64; kk += 16) {
        unsigned ah[4][4], bh[4][2];
        #pragma unroll
        for (int i = 0; i < 4; i++)
            ldsm4(ah[i], sA + aoff + i * 16 * RSM + kk);
        #pragma unroll
        for (int jp = 0; jp < 2; jp++) {
            unsigned t[4];
            ldsm4(t, sB + boff + jp * 16 * RSM + kk);
            bh[2*jp][0] = t[0]; bh[2*jp][1] = t[1];
            bh[2*jp+1][0] = t[2]; bh[2*jp+1][1] = t[3];
        }
        #pragma unroll
        for (int i = 0; i < 4; i++)
            #pragma unroll
            for (int j = 0; j < 4; j++)
                mma16816h(acc[i][j], ah[i], bh[j]);
    }
}

// grid (KN/128, VPAD/128); dyn smem = 2 stages * 2 * 128*72 halves = 73728 B
__global__ __launch_bounds__(256) void k_maingemm(const float* __restrict__ p_le,
                                                  const float* __restrict__ p_ls,
                                                  const float* __restrict__ bias) {
    extern __shared__ __half dsm[];
    int bm = blockIdx.x * 128, bn = blockIdx.y * 128;
    int tid = threadIdx.x;
    int w = tid >> 5, lane = tid & 31;
    int g = lane >> 2, q = lane & 3;
    int wm = w >> 2, wn = w & 3;
    int mi = lane >> 3, lr = lane & 7;
    int aoff = (wm * 64 + (mi & 1) * 8 + lr) * RSM + (mi >> 1) * 8;
    int boff = (wn * 32 + (mi >> 1) * 8 + lr) * RSM + (mi & 1) * 8;

    float accS[4][4][4], accT[4][4][4];
    #pragma unroll
    for (int i = 0; i < 4; i++)
        #pragma unroll
        for (int j = 0; j < 4; j++)
            #pragma unroll
            for (int c = 0; c < 4; c++) { accS[i][j][c] = 0.f; accT[i][j][c] = 0.f; }

    auto load_stage = [&](int s, int buf) {
        __half* base = dsm + buf * 18432;
        int k0 = s * 64;
        for (int c = tid; c < 2048; c += 256) {
            int mtx = c >> 10, wi = c & 1023;
            int row = wi >> 3, ch = wi & 7;
            if (mtx == 0)
                cp16(base + row * RSM + ch * 8,
                     g_A16 + (size_t)(bm + row) * KD + k0 + ch * 8);
            else
                cp16(base + 9216 + row * RSM + ch * 8,
                     g_B16 + (size_t)(bn + row) * KD + k0 + ch * 8);
        }
    };

    load_stage(0, 0); cpcommit();
    for (int s = 0; s < 15; s++) {
        int buf = s & 1;
        if (s < 14) { load_stage(s + 1, buf ^ 1); cpcommit(); cpwait<1>(); }
        else        { cpwait<0>(); }
        __syncthreads();
        if (s < 12) mg_compute(dsm + buf * 18432, aoff, boff, accS);
        else        mg_compute(dsm + buf * 18432, aoff, boff, accT);
        __syncthreads();
    }

    float eps = eps_of(*p_le);
    float inve = 1.f / eps;
    float scale = fminf(expf(*p_ls), 20.f);
    float sh = fmaxf(0.f, 2.f * inve - 9.8f);

    #pragma unroll
    for (int i = 0; i < 4; i++) {
        int m0 = bm + wm * 64 + i * 16 + g;
        int m1 = m0 + 8;
        float aa0 = g_AA[m0], aa1 = g_AA[m1];
        float bi0 = bias[m0], bi1 = bias[m1];
        #pragma unroll
        for (int j = 0; j < 4; j++) {
            #pragma unroll
            for (int c = 0; c < 2; c++) {
                int v = bn + wn * 32 + j * 8 + 2 * q + c;
                float bb = g_BB[v];
                int inr = (v < VN);
                float sv = accS[i][j][c], ab = sv + accT[i][j][c];
                float mah = fmaxf(aa0 + bb - 2.f * ab, 0.f);
                float t2 = 2.f * ab * inve;
                g_F[(size_t)m0 * VPAD + v] = scale * sv + bi0 - 0.3f * mah + 0.3f * t2;
                g_Kh[(size_t)m0 * VPAD + v] = inr ? __float2half(__expf(t2 - sh)) : __float2half(0.f);
                sv = accS[i][j][c + 2]; ab = sv + accT[i][j][c + 2];
                mah = fmaxf(aa1 + bb - 2.f * ab, 0.f);
                t2 = 2.f * ab * inve;
                g_F[(size_t)m1 * VPAD + v] = scale * sv + bi1 - 0.3f * mah + 0.3f * t2;
                g_Kh[(size_t)m1 * VPAD + v] = inr ? __float2half(__expf(t2 - sh)) : __float2half(0.f);
            }
        }
    }
}

// ---------------- sinkhorn init: v-tilde0 = exp(-bb/eps), pads 0 ----------------
__global__ void k_vinit(const float* __restrict__ p_le) {
    int v = blockIdx.x * blockDim.x + threadIdx.x;
    if (v >= VPAD) return;
    float inve = 1.f / eps_of(*p_le);
    g_v[v] = (v < VN) ? __expf(-g_BB[v] * inve) : 0.f;
}

// ---------------- fp16 sinkhorn: row pass (R8 shape) ----------------
__global__ __launch_bounds__(256) void k_rowlin() {
    int k = blockIdx.x, tid = threadIdx.x;
    const uint4* K8 = (const uint4*)&g_Kh[(size_t)k * VPAD];
    const float4* V4 = (const float4*)g_v;
    float s = 0.f;
    for (int i = tid; i < VPAD / 8; i += 256) {
        uint4 qq = K8[i];
        float4 a = V4[2 * i], b = V4[2 * i + 1];
        float2 p;
        p = __half22float2(*(__half2*)&qq.x); s += p.x * a.x + p.y * a.y;
        p = __half22float2(*(__half2*)&qq.y); s += p.x * a.z + p.y * a.w;
        p = __half22float2(*(__half2*)&qq.z); s += p.x * b.x + p.y * b.y;
        p = __half22float2(*(__half2*)&qq.w); s += p.x * b.z + p.y * b.w;
    }
    __shared__ float sr[256];
    sr[tid] = s; __syncthreads();
    for (int o = 128; o > 0; o >>= 1) { if (tid < o) sr[tid] += sr[tid + o]; __syncthreads(); }
    if (tid == 0) g_u[k] = 1.f / sr[0];
}

// ---------------- fp16 sinkhorn: col pass (R8 shape) ----------------
__global__ __launch_bounds__(256) void k_colpart() {
    __shared__ float su[256];
    int tid = threadIdx.x, cy = blockIdx.y;
    su[tid] = g_u[cy * 256 + tid];
    __syncthreads();
    int v2 = blockIdx.x * 512 + tid * 2;
    if (v2 >= VPAD) return;
    size_t base = (size_t)(cy * 256) * VPAD + v2;
    float sx0 = 0.f, sy0 = 0.f, sx1 = 0.f, sy1 = 0.f;
    #pragma unroll 4
    for (int k = 0; k < 256; k += 2) {
        float2 p0 = __half22float2(*(const __half2*)&g_Kh[base + (size_t)k * VPAD]);
        float2 p1 = __half22float2(*(const __half2*)&g_Kh[base + (size_t)(k + 1) * VPAD]);
        sx0 += p0.x * su[k];     sy0 += p0.y * su[k];
        sx1 += p1.x * su[k + 1]; sy1 += p1.y * su[k + 1];
    }
    *(float2*)&g_vden[cy][v2] = make_float2(sx0 + sx1, sy0 + sy1);
}

__global__ void k_vfin() {
    int v = blockIdx.x * blockDim.x + threadIdx.x;
    if (v >= VPAD) return;
    float den = g_vden[0][v] + g_vden[1][v];
    g_v[v] = (v < VN) ? 1.f / den : 0.f;
}

// last iteration: also produce log(v) inline
__global__ void k_vfin_last() {
    int v = blockIdx.x * blockDim.x + threadIdx.x;
    if (v >= VPAD) return;
    float den = g_vden[0][v] + g_vden[1][v];
    float vv = (v < VN) ? 1.f / den : 0.f;
    g_v[v] = vv;
    g_lvl[v] = (v < VN) ? __logf(vv) : 0.f;
}

// ---------------- final softmax: A computes row sums only (no write-back) ----------------
__global__ __launch_bounds__(256) void k_finalA(const float* __restrict__ p_le) {
    int k = blockIdx.x, tid = threadIdx.x;
    float inve = 1.f / eps_of(*p_le);
    float sh = fmaxf(0.f, 2.f * inve - 9.8f);
    float cs = 0.3f * (__logf(g_u[k]) - sh);
    const float* frow = g_F + (size_t)k * VPAD;
    float s = 0.f;
    for (int i = tid; i < 12564; i += 256) {
        float4 f4 = *(const float4*)&frow[i * 4];
        float4 l4 = *(const float4*)&g_lvl[i * 4];
        float x;
        x = f4.x + cs + 0.3f * l4.x; x = fminf(fmaxf(x, -30.f), 30.f); s += __expf(x - 30.f);
        x = f4.y + cs + 0.3f * l4.y; x = fminf(fmaxf(x, -30.f), 30.f); s += __expf(x - 30.f);
        x = f4.z + cs + 0.3f * l4.z; x = fminf(fmaxf(x, -30.f), 30.f); s += __expf(x - 30.f);
        x = f4.w + cs + 0.3f * l4.w; x = fminf(fmaxf(x, -30.f), 30.f); s += __expf(x - 30.f);
    }
    if (tid == 0) {  // tail element v = 50256
        float x = frow[50256] + cs + 0.3f * g_lvl[50256];
        x = fminf(fmaxf(x, -30.f), 30.f);
        s += __expf(x - 30.f);
    }
    __shared__ float sr[256];
    sr[tid] = s; __syncthreads();
    for (int o = 128; o > 0; o >>= 1) { if (tid < o) sr[tid] += sr[tid + o]; __syncthreads(); }
    if (tid == 0) g_rinv[k] = 1.f / sr[0];
}

// ---------------- finalB: recompute exp, write output (float4 loads, scalar stores) ----------------
__global__ __launch_bounds__(256) void k_finalB(const float* __restrict__ p_le,
                                                float* __restrict__ out) {
    int k = blockIdx.y, tid = threadIdx.x;
    float inve = 1.f / eps_of(*p_le);
    float sh = fmaxf(0.f, 2.f * inve - 9.8f);
    float cs = 0.3f * (__logf(g_u[k]) - sh);
    float ri = g_rinv[k];
    const float* frow = g_F + (size_t)k * VPAD;
    float* orow = out + (size_t)k * VN;
    int i4 = blockIdx.x * 256 + tid;   // group of 4
    if (i4 < 12564) {
        float4 f4 = *(const float4*)&frow[i4 * 4];
        float4 l4 = *(const float4*)&g_lvl[i4 * 4];
        float x;
        x = f4.x + cs + 0.3f * l4.x; x = fminf(fmaxf(x, -30.f), 30.f); orow[i4 * 4]     = __expf(x - 30.f) * ri;
        x = f4.y + cs + 0.3f * l4.y; x = fminf(fmaxf(x, -30.f), 30.f); orow[i4 * 4 + 1] = __expf(x - 30.f) * ri;
        x = f4.z + cs + 0.3f * l4.z; x = fminf(fmaxf(x, -30.f), 30.f); orow[i4 * 4 + 2] = __expf(x - 30.f) * ri;
        x = f4.w + cs + 0.3f * l4.w; x = fminf(fmaxf(x, -30.f), 30.f); orow[i4 * 4 + 3] = __expf(x - 30.f) * ri;
    } else if (i4 == 12564) {  // tail element v = 50256
        float x = frow[50256] + cs + 0.3f * g_lvl[50256];
        x = fminf(fmaxf(x, -30.f), 30.f);
        orow[50256] = __expf(x - 30.f) * ri;
    }
}

// ---------------- launch ----------------
extern "C" void kernel_launch(void* const* d_in, const int* in_sizes, int n_in,
                              void* d_out, int out_size) {
    const float* we   = (const float*)d_in[0];
    const float* anch = (const float*)d_in[1];
    const float* U    = (const float*)d_in[2];
    const float* p_le = (const float*)d_in[3];
    const float* p_ls = (const float*)d_in[4];
    const float* bias = (const float*)d_in[5];
    const float* Wp   = (const float*)d_in[6];
    float* out = (float*)d_out;

    cudaFuncSetAttribute(k_ubgemm,   cudaFuncAttributeMaxDynamicSharedMemorySize, 51712);
    cudaFuncSetAttribute(k_maingemm, cudaFuncAttributeMaxDynamicSharedMemorySize, 73728);

    k_init<<<1, 1>>>();
    k_idcheck<<<576, 256>>>(Wp);
    k_anchors<<<KN, 256>>>(anch, U);
    k_wnorm<<<VPAD / 8, 256>>>(we, Wp);
    k_ubgemm<<<VPAD / 128, 256, 51712>>>(U);

    dim3 gmain(KN / 128, VPAD / 128);
    k_maingemm<<<gmain, 256, 73728>>>(p_le, p_ls, bias);

    k_vinit<<<(VPAD + 255) / 256, 256>>>(p_le);
    dim3 gcol((VPAD + 511) / 512, 2);
    for (int it = 0; it < 10; it++) {
        k_rowlin<<<KN, 256>>>();
        k_colpart<<<gcol, 256>>>();
        if (it < 9) k_vfin<<<(VPAD + 255) / 256, 256>>>();
        else        k_vfin_last<<<(VPAD + 255) / 256, 256>>>();
    }

    k_finalA<<<KN, 256>>>(p_le);
    dim3 gf((12565 + 255) / 256, KN);
    k_finalB<<<gf, 256>>>(p_le, out);
}

// round 16
// speedup vs baseline: 1.0559x; 1.0559x over previous
#include <cuda_runtime.h>
#include <cuda_fp16.h>
#include <math.h>

#define VN 50257
#define VPAD 50304   // 393 * 128
#define KN 512
#define DN 768
#define RN 192
#define KD 960       // DN + RN
#define RSU 40       // ubgemm smem row stride (halves)
#define RSM 72       // maingemm smem row stride (halves), BK=64

// ---------------- scratch (static device globals; no allocation) ----------------
__device__ __half g_A16[KN * KD];
__device__ __half g_B16[(size_t)VPAD * KD];
__device__ float g_AA[KN];
__device__ float g_BB[VPAD];
__device__ float g_F[(size_t)KN * VPAD];      // scale*s + bias - 0.3*mah + 0.3*2ab/eps ; later exp(x-30)
__device__ __half g_Kh[(size_t)KN * VPAD];    // exp(2ab/eps - sh); 0 in pad cols
__device__ float g_u[KN];
__device__ float g_v[VPAD];
__device__ float g_lvl[VPAD];
__device__ float g_rinv[KN];
__device__ int   g_idflag;
__device__ unsigned g_barcnt = 0;
__device__ unsigned g_bargen = 0;

// ---------------- helpers ----------------
__device__ __forceinline__ void cp16(void* sm, const void* gp) {
    unsigned sa = (unsigned)__cvta_generic_to_shared(sm);
    asm volatile("cp.async.cg.shared.global [%0], [%1], 16;\n" :: "r"(sa), "l"(gp));
}
__device__ __forceinline__ void cpcommit() { asm volatile("cp.async.commit_group;\n"); }
template<int N> __device__ __forceinline__ void cpwait() {
    asm volatile("cp.async.wait_group %0;\n" :: "n"(N));
}
__device__ __forceinline__ void mma16816h(float c[4], const unsigned a[4], const unsigned b[2]) {
    asm volatile(
        "mma.sync.aligned.m16n8k16.row.col.f32.f16.f16.f32 "
        "{%0,%1,%2,%3}, {%4,%5,%6,%7}, {%8,%9}, {%0,%1,%2,%3};\n"
        : "+f"(c[0]), "+f"(c[1]), "+f"(c[2]), "+f"(c[3])
        : "r"(a[0]), "r"(a[1]), "r"(a[2]), "r"(a[3]), "r"(b[0]), "r"(b[1]));
}
__device__ __forceinline__ void ldsm4(unsigned r[4], const __half* p) {
    unsigned a = (unsigned)__cvta_generic_to_shared(p);
    asm volatile("ldmatrix.sync.aligned.m8n8.x4.shared.b16 {%0,%1,%2,%3}, [%4];\n"
                 : "=r"(r[0]), "=r"(r[1]), "=r"(r[2]), "=r"(r[3]) : "r"(a));
}
__device__ __forceinline__ float eps_of(float le) {
    return ((le > 20.f) ? le : log1pf(expf(le))) + 0.001f;
}

// ---------------- init ----------------
__global__ void k_init() { g_idflag = 1; }

__global__ void k_idcheck(const float* __restrict__ Wp) {
    int stride = gridDim.x * blockDim.x;
    for (int i = blockIdx.x * blockDim.x + threadIdx.x; i < DN * DN; i += stride) {
        float e = ((i / DN) == (i % DN)) ? 1.f : 0.f;
        if (Wp[i] != e) g_idflag = 0;
    }
}

// ---------------- anchors: normalize, Ua = a@U, AA from rounded fp16 ----------------
__global__ void k_anchors(const float* __restrict__ anch, const float* __restrict__ U) {
    __shared__ float sa[DN];
    __shared__ float sred[256];
    int k = blockIdx.x, tid = threadIdx.x;

    float ss = 0.f;
    for (int d = tid; d < DN; d += 256) { float x = anch[k * DN + d]; sa[d] = x; ss += x * x; }
    sred[tid] = ss; __syncthreads();
    for (int o = 128; o > 0; o >>= 1) { if (tid < o) sred[tid] += sred[tid + o]; __syncthreads(); }
    float inv = 1.f / fmaxf(sqrtf(sred[0]), 1e-12f);
    __syncthreads();
    float aa = 0.f;
    for (int d = tid; d < DN; d += 256) {
        float x = sa[d] * inv; sa[d] = x;
        __half h = __float2half(x);
        g_A16[k * KD + d] = h;
        float hr = __half2float(h);
        aa += hr * hr;
    }
    __syncthreads();
    if (tid < RN) {
        float acc = 0.f;
        for (int d = 0; d < DN; d++) acc += sa[d] * U[d * RN + tid];
        __half h = __float2half(acc);
        g_A16[k * KD + DN + tid] = h;
        float hr = __half2float(h);
        aa += hr * hr;
    }
    sred[tid] = aa; __syncthreads();
    for (int o = 128; o > 0; o >>= 1) { if (tid < o) sred[tid] += sred[tid + o]; __syncthreads(); }
    if (tid == 0) g_AA[k] = sred[0];
}

// ---------------- w_norm: warp-per-row, fp16 out, BB = sum of rounded squares ----------------
__global__ __launch_bounds__(256) void k_wnorm(const float* __restrict__ we,
                                               const float* __restrict__ Wp) {
    int warp = threadIdx.x >> 5, lane = threadIdx.x & 31;
    int v = blockIdx.x * 8 + warp;
    if (v >= VPAD) return;
    size_t gb = (size_t)v * KD;
    if (v >= VN) {
        #pragma unroll
        for (int c = 0; c < 6; c++) {
            int d = c * 128 + lane * 4;
            *(uint2*)&g_B16[gb + d] = make_uint2(0u, 0u);
        }
        if (lane == 0) g_BB[v] = 0.f;
        return;
    }
    int flag = g_idflag;
    float4 x[6];
    if (flag) {
        #pragma unroll
        for (int c = 0; c < 6; c++)
            x[c] = *(const float4*)&we[(size_t)v * DN + c * 128 + lane * 4];
    } else {
        for (int c = 0; c < 6; c++) {
            float r[4];
            for (int u2 = 0; u2 < 4; u2++) {
                int d = c * 128 + lane * 4 + u2;
                float acc = 0.f;
                for (int j = 0; j < DN; j++) acc += we[(size_t)v * DN + j] * Wp[d * DN + j];
                r[u2] = acc;
            }
            x[c] = make_float4(r[0], r[1], r[2], r[3]);
        }
    }
    float ss = 0.f;
    #pragma unroll
    for (int c = 0; c < 6; c++)
        ss += x[c].x * x[c].x + x[c].y * x[c].y + x[c].z * x[c].z + x[c].w * x[c].w;
    #pragma unroll
    for (int o = 16; o > 0; o >>= 1) ss += __shfl_xor_sync(0xffffffffu, ss, o);
    float inv = 1.f / fmaxf(sqrtf(ss), 1e-12f);
    float bb = 0.f;
    #pragma unroll
    for (int c = 0; c < 6; c++) {
        int d = c * 128 + lane * 4;
        float vl[4] = {x[c].x * inv, x[c].y * inv, x[c].z * inv, x[c].w * inv};
        __half h[4];
        #pragma unroll
        for (int t = 0; t < 4; t++) {
            h[t] = __float2half(vl[t]);
            float hr = __half2float(h[t]);
            bb += hr * hr;
        }
        *(__half2*)&g_B16[gb + d]     = __half2(h[0], h[1]);
        *(__half2*)&g_B16[gb + d + 2] = __half2(h[2], h[3]);
    }
    #pragma unroll
    for (int o = 16; o > 0; o >>= 1) bb += __shfl_xor_sync(0xffffffffu, bb, o);
    if (lane == 0) g_BB[v] = bb;
}

// ---------------- Ub = w_norm @ U (fp16, ldmatrix), fused BB add + v0 init ----------------
__global__ __launch_bounds__(256) void k_ubgemm(const float* __restrict__ U,
                                                const float* __restrict__ p_le) {
    extern __shared__ __half dsm[];
    __half* sW = dsm;              // 5120 halves
    __half* sU = dsm + 5120;       // 7680 halves
    float* sBB = (float*)(dsm + 12800);

    int bm = blockIdx.x * 128;
    int tid = threadIdx.x;
    int w = tid >> 5, lane = tid & 31;
    int g = lane >> 2, q = lane & 3;
    int wm = w >> 2, wn = w & 3;
    int mi = lane >> 3, lr = lane & 7;
    int aoff = (wm * 64 + (mi & 1) * 8 + lr) * RSU + (mi >> 1) * 8;
    int boff = (wn * 48 + (mi >> 1) * 8 + lr) * RSU + (mi & 1) * 8;
    if (tid < 128) sBB[tid] = 0.f;

    float acc[4][6][4];
    #pragma unroll
    for (int i = 0; i < 4; i++)
        #pragma unroll
        for (int j = 0; j < 6; j++)
            #pragma unroll
            for (int c = 0; c < 4; c++) acc[i][j][c] = 0.f;

    for (int s = 0; s < 24; s++) {
        int k0 = s * 32;
        __syncthreads();
        for (int c = tid; c < 512; c += 256) {
            int row = c >> 2, ch = c & 3;
            cp16(sW + row * RSU + ch * 8, g_B16 + (size_t)(bm + row) * KD + k0 + ch * 8);
        }
        for (int idx = tid; idx < 32 * RN; idx += 256) {
            int kp = idx / RN, n = idx % RN;
            sU[n * RSU + kp] = __float2half(U[(k0 + kp) * RN + n]);
        }
        cpcommit(); cpwait<0>();
        __syncthreads();

        #pragma unroll
        for (int kk = 0; kk < 32; kk += 16) {
            unsigned ah[4][4], bh[6][2];
            #pragma unroll
            for (int i = 0; i < 4; i++)
                ldsm4(ah[i], sW + aoff + i * 16 * RSU + kk);
            #pragma unroll
            for (int jp = 0; jp < 3; jp++) {
                unsigned t[4];
                ldsm4(t, sU + boff + jp * 16 * RSU + kk);
                bh[2*jp][0] = t[0]; bh[2*jp][1] = t[1];
                bh[2*jp+1][0] = t[2]; bh[2*jp+1][1] = t[3];
            }
            #pragma unroll
            for (int i = 0; i < 4; i++)
                #pragma unroll
                for (int j = 0; j < 6; j++)
                    mma16816h(acc[i][j], ah[i], bh[j]);
        }
    }

    #pragma unroll
    for (int i = 0; i < 4; i++) {
        int l0 = wm * 64 + i * 16 + g, l1 = l0 + 8;
        size_t m0 = (size_t)(bm + l0) * KD + DN;
        size_t m1 = (size_t)(bm + l1) * KD + DN;
        float p0 = 0.f, p1 = 0.f;
        #pragma unroll
        for (int j = 0; j < 6; j++) {
            int n0 = wn * 48 + j * 8 + 2 * q;
            __half h00 = __float2half(acc[i][j][0]);
            __half h01 = __float2half(acc[i][j][1]);
            __half h10 = __float2half(acc[i][j][2]);
            __half h11 = __float2half(acc[i][j][3]);
            float f00 = __half2float(h00), f01 = __half2float(h01);
            float f10 = __half2float(h10), f11 = __half2float(h11);
            p0 += f00 * f00 + f01 * f01;
            p1 += f10 * f10 + f11 * f11;
            g_B16[m0 + n0] = h00; g_B16[m0 + n0 + 1] = h01;
            g_B16[m1 + n0] = h10; g_B16[m1 + n0 + 1] = h11;
        }
        p0 += __shfl_xor_sync(0xffffffffu, p0, 1); p0 += __shfl_xor_sync(0xffffffffu, p0, 2);
        p1 += __shfl_xor_sync(0xffffffffu, p1, 1); p1 += __shfl_xor_sync(0xffffffffu, p1, 2);
        if (q == 0) { atomicAdd(&sBB[l0], p0); atomicAdd(&sBB[l1], p1); }
    }
    __syncthreads();
    if (tid < 128) {
        int v = bm + tid;
        float bbv = g_BB[v] + sBB[tid];
        g_BB[v] = bbv;
        float inve = 1.f / eps_of(*p_le);
        g_v[v] = (v < VN) ? __expf(-bbv * inve) : 0.f;   // sinkhorn v0, fused
    }
}

// ---------------- main GEMM (fp16, BK=64, dual acc) + fused epilogue ----------------
__device__ __forceinline__ void mg_compute(const __half* sb, int aoff, int boff,
                                           float acc[4][4][4]) {
    const __half* sA = sb;
    const __half* sB = sb + 9216;
    #pragma unroll
    for (int kk = 0; kk < 64; kk += 16) {
        unsigned ah[4][4], bh[4][2];
        #pragma unroll
        for (int i = 0; i < 4; i++)
            ldsm4(ah[i], sA + aoff + i * 16 * RSM + kk);
        #pragma unroll
        for (int jp = 0; jp < 2; jp++) {
            unsigned t[4];
            ldsm4(t, sB + boff + jp * 16 * RSM + kk);
            bh[2*jp][0] = t[0]; bh[2*jp][1] = t[1];
            bh[2*jp+1][0] = t[2]; bh[2*jp+1][1] = t[3];
        }
        #pragma unroll
        for (int i = 0; i < 4; i++)
            #pragma unroll
            for (int j = 0; j < 4; j++)
                mma16816h(acc[i][j], ah[i], bh[j]);
    }
}

// grid (KN/128, VPAD/128); dyn smem = 2 stages * 2 * 128*72 halves = 73728 B
__global__ __launch_bounds__(256) void k_maingemm(const float* __restrict__ p_le,
                                                  const float* __restrict__ p_ls,
                                                  const float* __restrict__ bias) {
    extern __shared__ __half dsm[];
    int bm = blockIdx.x * 128, bn = blockIdx.y * 128;
    int tid = threadIdx.x;
    int w = tid >> 5, lane = tid & 31;
    int g = lane >> 2, q = lane & 3;
    int wm = w >> 2, wn = w & 3;
    int mi = lane >> 3, lr = lane & 7;
    int aoff = (wm * 64 + (mi & 1) * 8 + lr) * RSM + (mi >> 1) * 8;
    int boff = (wn * 32 + (mi >> 1) * 8 + lr) * RSM + (mi & 1) * 8;

    float accS[4][4][4], accT[4][4][4];
    #pragma unroll
    for (int i = 0; i < 4; i++)
        #pragma unroll
        for (int j = 0; j < 4; j++)
            #pragma unroll
            for (int c = 0; c < 4; c++) { accS[i][j][c] = 0.f; accT[i][j][c] = 0.f; }

    auto load_stage = [&](int s, int buf) {
        __half* base = dsm + buf * 18432;
        int k0 = s * 64;
        for (int c = tid; c < 2048; c += 256) {
            int mtx = c >> 10, wi = c & 1023;
            int row = wi >> 3, ch = wi & 7;
            if (mtx == 0)
                cp16(base + row * RSM + ch * 8,
                     g_A16 + (size_t)(bm + row) * KD + k0 + ch * 8);
            else
                cp16(base + 9216 + row * RSM + ch * 8,
                     g_B16 + (size_t)(bn + row) * KD + k0 + ch * 8);
        }
    };

    load_stage(0, 0); cpcommit();
    for (int s = 0; s < 15; s++) {
        int buf = s & 1;
        if (s < 14) { load_stage(s + 1, buf ^ 1); cpcommit(); cpwait<1>(); }
        else        { cpwait<0>(); }
        __syncthreads();
        if (s < 12) mg_compute(dsm + buf * 18432, aoff, boff, accS);
        else        mg_compute(dsm + buf * 18432, aoff, boff, accT);
        __syncthreads();
    }

    float eps = eps_of(*p_le);
    float inve = 1.f / eps;
    float scale = fminf(expf(*p_ls), 20.f);
    float sh = fmaxf(0.f, 2.f * inve - 9.8f);

    #pragma unroll
    for (int i = 0; i < 4; i++) {
        int m0 = bm + wm * 64 + i * 16 + g;
        int m1 = m0 + 8;
        float aa0 = g_AA[m0], aa1 = g_AA[m1];
        float bi0 = bias[m0], bi1 = bias[m1];
        #pragma unroll
        for (int j = 0; j < 4; j++) {
            #pragma unroll
            for (int c = 0; c < 2; c++) {
                int v = bn + wn * 32 + j * 8 + 2 * q + c;
                float bb = g_BB[v];
                int inr = (v < VN);
                float sv = accS[i][j][c], ab = sv + accT[i][j][c];
                float mah = fmaxf(aa0 + bb - 2.f * ab, 0.f);
                float t2 = 2.f * ab * inve;
                g_F[(size_t)m0 * VPAD + v] = scale * sv + bi0 - 0.3f * mah + 0.3f * t2;
                g_Kh[(size_t)m0 * VPAD + v] = inr ? __float2half(__expf(t2 - sh)) : __float2half(0.f);
                sv = accS[i][j][c + 2]; ab = sv + accT[i][j][c + 2];
                mah = fmaxf(aa1 + bb - 2.f * ab, 0.f);
                t2 = 2.f * ab * inve;
                g_F[(size_t)m1 * VPAD + v] = scale * sv + bi1 - 0.3f * mah + 0.3f * t2;
                g_Kh[(size_t)m1 * VPAD + v] = inr ? __float2half(__expf(t2 - sh)) : __float2half(0.f);
            }
        }
    }
}

// ---------------- fused sinkhorn iteration: row pass + grid barrier + col pass ----------------
// grid 512, block 256, min 4 CTAs/SM guaranteed -> all 512 co-resident (148*4=592)
__global__ __launch_bounds__(256, 4) void k_sinkiter(int lastit) {
    __shared__ float sr[256];
    __shared__ float su[KN];
    __shared__ float2 part[4][64];
    int tid = threadIdx.x, cta = blockIdx.x;

    // ---- phase A: u[cta] = 1 / (Kh[cta,:] . v) ----
    {
        const uint4* K8 = (const uint4*)&g_Kh[(size_t)cta * VPAD];
        const float4* V4 = (const float4*)g_v;
        float s = 0.f;
        for (int i = tid; i < VPAD / 8; i += 256) {
            uint4 qq = K8[i];
            float4 a = V4[2 * i], b = V4[2 * i + 1];
            float2 p;
            p = __half22float2(*(__half2*)&qq.x); s += p.x * a.x + p.y * a.y;
            p = __half22float2(*(__half2*)&qq.y); s += p.x * a.z + p.y * a.w;
            p = __half22float2(*(__half2*)&qq.z); s += p.x * b.x + p.y * b.y;
            p = __half22float2(*(__half2*)&qq.w); s += p.x * b.z + p.y * b.w;
        }
        sr[tid] = s; __syncthreads();
        for (int o = 128; o > 0; o >>= 1) { if (tid < o) sr[tid] += sr[tid + o]; __syncthreads(); }
        if (tid == 0) g_u[cta] = 1.f / sr[0];
    }

    // ---- grid barrier (sense-reversal; monotonic generation is replay-safe) ----
    __threadfence();
    __syncthreads();
    if (tid == 0) {
        unsigned gen = atomicAdd(&g_bargen, 0u);
        unsigned prev = atomicAdd(&g_barcnt, 1u);
        if (prev == 511u) {
            g_barcnt = 0;
            __threadfence();
            atomicExch(&g_bargen, gen + 1u);
        } else {
            while (atomicAdd(&g_bargen, 0u) == gen) {}
            __threadfence();
        }
    }
    __syncthreads();

    // ---- phase B: col tile (CTAs 0..392 each own 128 columns; 4-way k-split) ----
    su[tid] = g_u[tid];
    su[tid + 256] = g_u[tid + 256];
    __syncthreads();
    if (cta < 393) {
        int pair = tid & 63, kq = tid >> 6;
        int c0 = cta * 128 + pair * 2;
        const __half2* col = (const __half2*)&g_Kh[(size_t)(kq * 128) * VPAD + c0];
        const float* suk = su + kq * 128;
        float sx = 0.f, sy = 0.f;
        #pragma unroll 8
        for (int k = 0; k < 128; k++) {
            float2 p = __half22float2(col[(size_t)k * (VPAD / 2)]);
            sx += p.x * suk[k];
            sy += p.y * suk[k];
        }
        part[kq][pair] = make_float2(sx, sy);
        __syncthreads();
        if (tid < 64) {
            float dx = part[0][tid].x + part[1][tid].x + part[2][tid].x + part[3][tid].x;
            float dy = part[0][tid].y + part[1][tid].y + part[2][tid].y + part[3][tid].y;
            int c = cta * 128 + tid * 2;
            float vx = (c < VN) ? 1.f / dx : 0.f;
            float vy = (c + 1 < VN) ? 1.f / dy : 0.f;
            *(float2*)&g_v[c] = make_float2(vx, vy);
            if (lastit) {
                g_lvl[c]     = (c < VN)     ? __logf(vx) : 0.f;
                g_lvl[c + 1] = (c + 1 < VN) ? __logf(vy) : 0.f;
            }
        }
    }
}

// ---------------- final softmax: finalA writes exp(x-30) in-place (R14 best form) ----------------
__global__ __launch_bounds__(256) void k_finalA(const float* __restrict__ p_le) {
    int k = blockIdx.x, tid = threadIdx.x;
    float inve = 1.f / eps_of(*p_le);
    float sh = fmaxf(0.f, 2.f * inve - 9.8f);
    float cs = 0.3f * (__logf(g_u[k]) - sh);
    float* frow = g_F + (size_t)k * VPAD;
    float s = 0.f;
    for (int i = tid; i < 12564; i += 256) {
        float4 f4 = *(const float4*)&frow[i * 4];
        float4 l4 = *(const float4*)&g_lvl[i * 4];
        float4 e4;
        float x;
        x = f4.x + cs + 0.3f * l4.x; x = fminf(fmaxf(x, -30.f), 30.f); e4.x = __expf(x - 30.f);
        x = f4.y + cs + 0.3f * l4.y; x = fminf(fmaxf(x, -30.f), 30.f); e4.y = __expf(x - 30.f);
        x = f4.z + cs + 0.3f * l4.z; x = fminf(fmaxf(x, -30.f), 30.f); e4.z = __expf(x - 30.f);
        x = f4.w + cs + 0.3f * l4.w; x = fminf(fmaxf(x, -30.f), 30.f); e4.w = __expf(x - 30.f);
        s += e4.x + e4.y + e4.z + e4.w;
        *(float4*)&frow[i * 4] = e4;
    }
    if (tid == 0) {  // tail element v = 50256
        float x = frow[50256] + cs + 0.3f * g_lvl[50256];
        x = fminf(fmaxf(x, -30.f), 30.f);
        float e = __expf(x - 30.f);
        s += e;
        frow[50256] = e;
    }
    __shared__ float sr[256];
    sr[tid] = s; __syncthreads();
    for (int o = 128; o > 0; o >>= 1) { if (tid < o) sr[tid] += sr[tid + o]; __syncthreads(); }
    if (tid == 0) g_rinv[k] = 1.f / sr[0];
}

__global__ __launch_bounds__(256) void k_finalB(float* __restrict__ out) {
    int k = blockIdx.y;
    int v = blockIdx.x * 256 + threadIdx.x;
    if (v >= VN) return;
    out[(size_t)k * VN + v] = g_F[(size_t)k * VPAD + v] * g_rinv[k];
}

// ---------------- launch ----------------
extern "C" void kernel_launch(void* const* d_in, const int* in_sizes, int n_in,
                              void* d_out, int out_size) {
    const float* we   = (const float*)d_in[0];
    const float* anch = (const float*)d_in[1];
    const float* U    = (const float*)d_in[2];
    const float* p_le = (const float*)d_in[3];
    const float* p_ls = (const float*)d_in[4];
    const float* bias = (const float*)d_in[5];
    const float* Wp   = (const float*)d_in[6];
    float* out = (float*)d_out;

    cudaFuncSetAttribute(k_ubgemm,   cudaFuncAttributeMaxDynamicSharedMemorySize, 26112);
    cudaFuncSetAttribute(k_maingemm, cudaFuncAttributeMaxDynamicSharedMemorySize, 73728);

    k_init<<<1, 1>>>();
    k_idcheck<<<576, 256>>>(Wp);
    k_anchors<<<KN, 256>>>(anch, U);
    k_wnorm<<<VPAD / 8, 256>>>(we, Wp);
    k_ubgemm<<<VPAD / 128, 256, 26112>>>(U, p_le);

    dim3 gmain(KN / 128, VPAD / 128);
    k_maingemm<<<gmain, 256, 73728>>>(p_le, p_ls, bias);

    for (int it = 0; it < 10; it++)
        k_sinkiter<<<512, 256>>>(it == 9 ? 1 : 0);

    k_finalA<<<KN, 256>>>(p_le);
    dim3 gf((VN + 255) / 256, KN);
    k_finalB<<<gf, 256>>>(out);
}